// round 15
// baseline (speedup 1.0000x reference)
#include <cuda_runtime.h>
#include <cuda_fp16.h>
#include <math.h>
#include <stdint.h>

#define TT      256
#define BBATCH  256
#define HHID    512
#define MROWS   65536
#define NGATE   2048
#define STATE_SZ (BBATCH*HHID)
#define STACKED_SZ ((size_t)TT*BBATCH*HHID)

__device__ float  d_h1[(size_t)MROWS * 128];
__device__ __half d_h2h[(size_t)MROWS * 64];
__device__ float  d_wp[(size_t)64 * NGATE];
__device__ float  d_bp[NGATE];
__device__ __half d_hxh[2][STATE_SZ];
__device__ float  d_mask[4];
__device__ unsigned g_arrive[4][32];   // monotone per-(mt,ng) step counters

__device__ __forceinline__ float ftf32(float x) {
    float r; asm("cvt.rna.tf32.f32 %0, %1;" : "=f"(r) : "f"(x)); return r;
}
__device__ __forceinline__ void mma8(float c[4],
                                     uint32_t a0, uint32_t a1, uint32_t a2, uint32_t a3,
                                     uint32_t b0, uint32_t b1) {
    asm volatile(
        "mma.sync.aligned.m16n8k8.row.col.f32.tf32.tf32.f32 "
        "{%0,%1,%2,%3},{%4,%5,%6,%7},{%8,%9},{%0,%1,%2,%3};\n"
        : "+f"(c[0]), "+f"(c[1]), "+f"(c[2]), "+f"(c[3])
        : "r"(a0), "r"(a1), "r"(a2), "r"(a3), "r"(b0), "r"(b1));
}
__device__ __forceinline__ void mma16(float c[4],
                                      uint32_t a0, uint32_t a1, uint32_t a2, uint32_t a3,
                                      uint32_t b0, uint32_t b1) {
    asm volatile(
        "mma.sync.aligned.m16n8k16.row.col.f32.f16.f16.f32 "
        "{%0,%1,%2,%3},{%4,%5,%6,%7},{%8,%9},{%0,%1,%2,%3};\n"
        : "+f"(c[0]), "+f"(c[1]), "+f"(c[2]), "+f"(c[3])
        : "r"(a0), "r"(a1), "r"(a2), "r"(a3), "r"(b0), "r"(b1));
}
__device__ __forceinline__ void ldsm4(uint32_t& r0, uint32_t& r1, uint32_t& r2,
                                      uint32_t& r3, uint32_t a) {
    asm volatile("ldmatrix.sync.aligned.m8n8.x4.shared.b16 {%0,%1,%2,%3}, [%4];"
                 : "=r"(r0), "=r"(r1), "=r"(r2), "=r"(r3) : "r"(a));
}
__device__ __forceinline__ void cpa16(uint32_t dst, const void* src) {
    asm volatile("cp.async.cg.shared.global [%0], [%1], 16;\n" :: "r"(dst), "l"(src));
}
#define CP_COMMIT() asm volatile("cp.async.commit_group;\n" ::: "memory")
#define CP_WAIT(n)  asm volatile("cp.async.wait_group %0;\n" :: "n"(n) : "memory")

__device__ __forceinline__ float fsig(float x) {
    return __fdividef(1.f, 1.f + __expf(-x));
}
__device__ __forceinline__ float ftanh(float x) {
    return __fdividef(2.f, 1.f + __expf(-2.f * x)) - 1.f;
}

// ---------------------------------------------------------------------------
// Encoder tf32 GEMM (proven, unchanged)
// ---------------------------------------------------------------------------
template<int RELU, int OUTH>
__global__ void __launch_bounds__(128) gemm_tf32_kernel(
    const float* __restrict__ A, const float* __restrict__ B,
    const float* __restrict__ bias, void* __restrict__ Cv,
    int M, int N, int K, int ldb)
{
    __shared__ float As[2][2304];
    __shared__ float Bs[2][2304];

    const int tid = threadIdx.x;
    const int lane = tid & 31, warp = tid >> 5;
    const int m0 = blockIdx.y * 64, n0 = blockIdx.x * 64;
    const int wm = (warp >> 1) * 32, wn = (warp & 1) * 32;
    const int g = lane >> 2, tg = lane & 3;

    float acc[2][4][4];
#pragma unroll
    for (int i = 0; i < 2; i++)
#pragma unroll
        for (int j = 0; j < 4; j++)
#pragma unroll
            for (int e = 0; e < 4; e++) acc[i][j][e] = 0.f;

    const int NC = K >> 5;
    float4 ra[4], rb[4];

    auto loadg = [&](int kc) {
#pragma unroll
        for (int p = 0; p < 4; p++) {
            int idx = p * 512 + tid * 4;
            int am = idx >> 5, ak = idx & 31;
            ra[p] = *(const float4*)(A + (size_t)(m0 + am) * K + kc + ak);
            int bk = idx >> 6, bn = idx & 63;
            rb[p] = *(const float4*)(B + (size_t)(kc + bk) * ldb + n0 + bn);
        }
    };
    auto store = [&](int buf) {
#pragma unroll
        for (int p = 0; p < 4; p++) {
            int idx = p * 512 + tid * 4;
            int am = idx >> 5, ak = idx & 31;
            float4 v = ra[p];
            v.x = ftf32(v.x); v.y = ftf32(v.y); v.z = ftf32(v.z); v.w = ftf32(v.w);
            *(float4*)&As[buf][am * 36 + ak] = v;
            int bk = idx >> 6, bn = idx & 63;
            float4 w = rb[p];
            w.x = ftf32(w.x); w.y = ftf32(w.y); w.z = ftf32(w.z); w.w = ftf32(w.w);
            *(float4*)&Bs[buf][bk * 72 + bn] = w;
        }
    };
    auto compute = [&](int buf) {
#pragma unroll
        for (int kk = 0; kk < 32; kk += 8) {
            uint32_t a[2][4];
#pragma unroll
            for (int mf = 0; mf < 2; mf++) {
                int rbase = wm + mf * 16 + g;
                a[mf][0] = __float_as_uint(As[buf][rbase * 36 + kk + tg]);
                a[mf][1] = __float_as_uint(As[buf][(rbase + 8) * 36 + kk + tg]);
                a[mf][2] = __float_as_uint(As[buf][rbase * 36 + kk + tg + 4]);
                a[mf][3] = __float_as_uint(As[buf][(rbase + 8) * 36 + kk + tg + 4]);
            }
#pragma unroll
            for (int nf = 0; nf < 4; nf++) {
                uint32_t b0 = __float_as_uint(Bs[buf][(kk + tg) * 72 + wn + nf * 8 + g]);
                uint32_t b1 = __float_as_uint(Bs[buf][(kk + tg + 4) * 72 + wn + nf * 8 + g]);
                mma8(acc[0][nf], a[0][0], a[0][1], a[0][2], a[0][3], b0, b1);
                mma8(acc[1][nf], a[1][0], a[1][1], a[1][2], a[1][3], b0, b1);
            }
        }
    };

    loadg(0); store(0); __syncthreads();
    for (int c = 0; c < NC; c++) {
        int cur = c & 1;
        if (c + 1 < NC) loadg((c + 1) * 32);
        compute(cur);
        if (c + 1 < NC) store(cur ^ 1);
        __syncthreads();
    }

#pragma unroll
    for (int mf = 0; mf < 2; mf++) {
        int r = m0 + wm + mf * 16 + g;
#pragma unroll
        for (int nf = 0; nf < 4; nf++) {
            int col = n0 + wn + nf * 8 + 2 * tg;
            float b0 = bias[col], b1 = bias[col + 1];
            float v0 = acc[mf][nf][0] + b0;
            float v1 = acc[mf][nf][1] + b1;
            float v2 = acc[mf][nf][2] + b0;
            float v3 = acc[mf][nf][3] + b1;
            if (RELU) {
                v0 = fmaxf(v0, 0.f); v1 = fmaxf(v1, 0.f);
                v2 = fmaxf(v2, 0.f); v3 = fmaxf(v3, 0.f);
            }
            if (OUTH) {
                __half* C = (__half*)Cv;
                *(__half2*)(C + (size_t)r * N + col)       = __floats2half2_rn(v0, v1);
                *(__half2*)(C + (size_t)(r + 8) * N + col) = __floats2half2_rn(v2, v3);
            } else {
                float* C = (float*)Cv;
                float2 p0; p0.x = v0; p0.y = v1;
                float2 p1; p1.x = v2; p1.y = v3;
                *(float2*)(C + (size_t)r * N + col) = p0;
                *(float2*)(C + (size_t)(r + 8) * N + col) = p1;
            }
        }
    }
}

// ---------------------------------------------------------------------------
__global__ void __launch_bounds__(256) wprime_kernel(
    const float* __restrict__ W3, const float* __restrict__ GW, float* __restrict__ WP)
{
    __shared__ float Asw[64][33];
    __shared__ float Bsw[32][65];
    int tid = threadIdx.x;
    int n0 = blockIdx.x * 64;
    int col = tid & 63;
    int rg = (tid >> 6) * 16;
    float acc[16];
#pragma unroll
    for (int i = 0; i < 16; i++) acc[i] = 0.f;

    for (int kc = 0; kc < 512; kc += 32) {
#pragma unroll
        for (int p = 0; p < 8; p++) {
            int idx = p * 256 + tid;
            int r = idx >> 5, k = idx & 31;
            Asw[r][k] = W3[(size_t)r * 512 + kc + k];
            int bk = idx >> 6, bc = idx & 63;
            Bsw[bk][bc] = GW[(size_t)(kc + bk) * NGATE + n0 + bc];
        }
        __syncthreads();
#pragma unroll 8
        for (int k = 0; k < 32; k++) {
            float bv = Bsw[k][col];
#pragma unroll
            for (int i = 0; i < 16; i++) acc[i] += Asw[rg + i][k] * bv;
        }
        __syncthreads();
    }
#pragma unroll
    for (int i = 0; i < 16; i++)
        WP[(size_t)(rg + i) * NGATE + n0 + col] = acc[i];
}

__global__ void __launch_bounds__(32) bprime_kernel(
    const float* __restrict__ eb3, const float* __restrict__ GW,
    const float* __restrict__ gb, float* __restrict__ BP)
{
    int n = blockIdx.x * 32 + threadIdx.x;
    float s = gb[n];
#pragma unroll 8
    for (int k = 0; k < 512; k++) s += eb3[k] * GW[(size_t)k * NGATE + n];
    BP[n] = s;
}

__global__ void mask_kernel(const float* __restrict__ w1, const float* __restrict__ b1,
                            const float* __restrict__ w2, const float* __restrict__ b2)
{
    if (threadIdx.x == 0 && blockIdx.x == 0) {
        float h[8];
        for (int j = 0; j < 8; j++) {
            float s = b1[j];
            for (int i = 0; i < 4; i++) s += w1[i * 8 + j];
            h[j] = tanhf(s);
        }
        float o[4], mx = -1e30f;
        for (int k = 0; k < 4; k++) {
            float s = b2[k];
            for (int j = 0; j < 8; j++) s += h[j] * w2[j * 4 + k];
            o[k] = s; mx = fmaxf(mx, s);
        }
        float e[4], se = 0.f;
        for (int k = 0; k < 4; k++) { e[k] = expf(o[k] - mx); se += e[k]; }
        for (int k = 0; k < 4; k++) d_mask[k] = e[k] / se;
    }
}

// ---------------------------------------------------------------------------
// Persistent recurrence: dual-ldmatrix fp16 mma + decentralized flag polling.
// Grid = 128 CTAs (4 m-tiles x 32 n-groups), 8 warps: gate = w&3, wm=(w>>2)*32.
// K = 576: chunk0 = h2 x W' (k 512..575); hx = 2 x 256k commit groups.
// Each thread's cp.async granules touch exactly one producer's h-cols
// (ng = c*8 + ((tid&15)>>1)), so it polls ONLY that flag -> no acquire sync.
// Loads are issued BEFORE chunk0 compute so chunk0 hides the hx L2 latency.
// Accumulation order identical to R14 (chunk0, c1..c4) -> bit-identical.
// ---------------------------------------------------------------------------
#define PS_SMEM_BYTES 166144
#define A_OFF   74752
#define H2_OFF  140288
#define GSM_OFF 148480
#define BSM_OFF 165888

__global__ void __launch_bounds__(256) lstm_persistent(
    const float* __restrict__ gate_w, const float* __restrict__ wp,
    const float* __restrict__ bp, float* __restrict__ out)
{
    extern __shared__ __align__(16) char smem[];
    __half* Bs  = (__half*)smem;
    float*  gsm = (float*)(smem + GSM_OFF);
    float*  bsm = (float*)(smem + BSM_OFF);
    const uint32_t sbase = (uint32_t)__cvta_generic_to_shared(smem);

    const int tid  = threadIdx.x;
    const int lane = tid & 31, warp = tid >> 5;
    const int g = lane >> 2, tg = lane & 3;
    const int gate = warp & 3;
    const int wn = gate * 16;
    const int wm = (warp >> 2) * 32;

    const int ng = blockIdx.x & 31;     // 16 h cols
    const int mt = blockIdx.x >> 5;     // m-tile
    const int m0 = mt * 64;
    const int h0 = ng * 16;

    const float* Wh = gate_w + (size_t)512 * NGATE;

    unsigned fbase = *((volatile unsigned*)&g_arrive[mt][ng]);

    // ---- preload weights into Bs[n][k] (half), k<512 Wh, k>=512 W' ----
    for (int it = tid; it < 64 * 576; it += 256) {
        int n = it & 63;
        int k = it >> 6;
        int gt = n >> 4, j = n & 15;
        float v;
        if (k < 512) v = Wh[(size_t)k * NGATE + gt * 512 + h0 + j];
        else         v = wp[(size_t)(k - 512) * NGATE + gt * 512 + h0 + j];
        Bs[n * 584 + k] = __float2half_rn(v);
    }
    if (tid < 64) {
        int gt = tid >> 4, j = tid & 15;
        bsm[tid] = bp[gt * 512 + h0 + j];
    }
    __syncthreads();

    const float mk = d_mask[gate];
    float cx[4] = {0.f, 0.f, 0.f, 0.f};
    const int um = tid >> 2, uj = (tid & 3) * 4;
    const int myg = (tid & 15) >> 1;    // producer group this thread's loads need

    // 128k hx chunk -> buffer buf (NO commit; caller groups commits)
    auto issueA_nc = [&](int buf, const __half* src) {
#pragma unroll
        for (int p = 0; p < 4; p++) {
            int idx = p * 256 + tid;
            int row = idx >> 4, gr = idx & 15;
            uint32_t dst = sbase + (uint32_t)(A_OFF + buf * 16384 + row * 256
                                              + ((gr ^ (row & 7)) << 4));
            cpa16(dst, src + (size_t)row * HHID + gr * 8);
        }
    };
    // h2 chunk (64 rows x 64 halves) -> single h2 buffer (commits)
    auto issueH2 = [&](const __half* src) {
#pragma unroll
        for (int p = 0; p < 2; p++) {
            int idx = p * 256 + tid;
            int row = idx >> 3, gr = idx & 7;
            uint32_t dst = sbase + (uint32_t)(H2_OFF + row * 128
                                              + ((gr ^ (row & 7)) << 4));
            cpa16(dst, src + (size_t)row * 64 + gr * 8);
        }
        CP_COMMIT();
    };

    float acc[2][2][4];
    // A via ldmatrix.x4 (proven), B via ldmatrix.x4 (proven):
    //   matrix i = {nf = i>>1, k-half = (i&1)*8}; lane rows wn+(mi>>1)*8+(lane&7).
    const int mi = lane >> 3;
    const int rA0 = wm + (mi & 1) * 8 + (lane & 7);
    const uint32_t bbase = sbase
        + (uint32_t)(((wn + (mi >> 1) * 8 + (lane & 7)) * 584 + (mi & 1) * 8) * 2);
    auto computeL = [&](uint32_t aoff, int RS, int koff, int ks, int NKK) {
        for (int kk16 = ks; kk16 < ks + NKK; kk16++) {
            const int kg = kk16 * 2 + (mi >> 1);
            uint32_t a0, a1, a2, a3, c0, c1, c2, c3;
            {
                int row = rA0;
                uint32_t ad = sbase + aoff
                    + (uint32_t)((row * RS + ((kg ^ (row & 7)) << 3)) << 1);
                ldsm4(a0, a1, a2, a3, ad);
            }
            {
                int row = rA0 + 16;
                uint32_t ad = sbase + aoff
                    + (uint32_t)((row * RS + ((kg ^ (row & 7)) << 3)) << 1);
                ldsm4(c0, c1, c2, c3, ad);
            }
            uint32_t b0, b1, b2, b3;
            ldsm4(b0, b1, b2, b3, bbase + (uint32_t)((koff + kk16 * 16) * 2));
            mma16(acc[0][0], a0, a1, a2, a3, b0, b1);
            mma16(acc[1][0], c0, c1, c2, c3, b0, b1);
            mma16(acc[0][1], a0, a1, a2, a3, b2, b3);
            mma16(acc[1][1], c0, c1, c2, c3, b2, b3);
        }
    };

    // prologue: h2[0] -> h2 buffer
    issueH2(d_h2h + (size_t)m0 * 64);

    for (int t = 0; t < TT; t++) {
        const __half* hx_in  = d_hxh[t & 1];
        __half*       hx_out = d_hxh[(t + 1) & 1];

#pragma unroll
        for (int i = 0; i < 2; i++)
#pragma unroll
            for (int j = 0; j < 2; j++)
#pragma unroll
                for (int e = 0; e < 4; e++) acc[i][j][e] = 0.f;

        CP_WAIT(0);
        __syncthreads();

        if (t == 0) {
            computeL(H2_OFF, 64, 512, 0, 4);             // full chunk 0 (hx=0)
            __syncthreads();                             // all H2 reads done
            issueH2(d_h2h + (size_t)(BBATCH + m0) * 64); // h2[1]
        } else {
            // per-thread flag polls (each thread needs exactly one producer
            // per chunk: ng = c*8 + myg), then issue loads; NO acquire sync.
            const unsigned tgt = fbase + (unsigned)t;
            const __half* hxm = hx_in + (size_t)m0 * HHID;
            unsigned v;
#pragma unroll
            for (int c = 0; c < 4; c++) {
                const unsigned* fp = &g_arrive[mt][c * 8 + myg];
                do {
                    asm volatile("ld.acquire.gpu.global.u32 %0, [%1];"
                                 : "=r"(v) : "l"(fp));
                } while ((int)(v - tgt) < 0);
                issueA_nc(c, hxm + c * 128);
                if (c == 1 || c == 3) CP_COMMIT();       // G1={c1,c2}, G2={c3,c4}
            }

            computeL(H2_OFF, 64, 512, 0, 4);             // chunk0 (hides G1 L2 trip)

            CP_WAIT(1); __syncthreads();                 // G1 ready; H2 reads retired
            {   // G3: h2[t+1] prefetch — safe (no pending H2 readers)
                int tn = (t + 1 < TT) ? (t + 1) : 0;
                issueH2(d_h2h + ((size_t)tn * BBATCH + m0) * 64);
            }
            computeL(A_OFF,         128, 0,   0, 8);     // c1
            computeL(A_OFF + 16384, 128, 128, 0, 8);     // c2
            CP_WAIT(1); __syncthreads();                 // G2 ready (G3 may pend)
            computeL(A_OFF + 32768, 128, 256, 0, 8);     // c3
            computeL(A_OFF + 49152, 128, 384, 0, 8);     // c4
        }

        // ---- epilogue: bias + activation*mask -> gsm (own warp tile) ----
#pragma unroll
        for (int mf = 0; mf < 2; mf++) {
            int r0 = wm + mf * 16 + g;
#pragma unroll
            for (int nf = 0; nf < 2; nf++) {
                int j0 = nf * 8 + 2 * tg;
                float b0 = bsm[gate * 16 + j0], b1 = bsm[gate * 16 + j0 + 1];
                float p0 = acc[mf][nf][0] + b0;
                float p1 = acc[mf][nf][1] + b1;
                float p2 = acc[mf][nf][2] + b0;
                float p3 = acc[mf][nf][3] + b1;
                float a0, a1, a2, a3;
                if (gate == 2) {
                    a0 = ftanh(p0); a1 = ftanh(p1); a2 = ftanh(p2); a3 = ftanh(p3);
                } else {
                    a0 = fsig(p0); a1 = fsig(p1); a2 = fsig(p2); a3 = fsig(p3);
                }
                float* gp = gsm + gate * 1088;
                gp[r0 * 17 + j0]           = a0 * mk;
                gp[r0 * 17 + j0 + 1]       = a1 * mk;
                gp[(r0 + 8) * 17 + j0]     = a2 * mk;
                gp[(r0 + 8) * 17 + j0 + 1] = a3 * mk;
            }
        }
        __syncthreads();

        // ---- cell update (cx register-resident); hx fp16 store first ----
        float4 h4, c4v;
        float* hp = &h4.x; float* cp = &c4v.x;
#pragma unroll
        for (int q = 0; q < 4; q++) {
            int jj = uj + q;
            float fv = gsm[0 * 1088 + um * 17 + jj];
            float iv = gsm[1 * 1088 + um * 17 + jj];
            float gv = gsm[2 * 1088 + um * 17 + jj];
            float ov = gsm[3 * 1088 + um * 17 + jj];
            cx[q] = fv * cx[q] + iv * gv;
            cp[q] = cx[q];
            hp[q] = ov * ftanh(cx[q]);
        }
        int gi = (m0 + um) * HHID + h0 + uj;
        {
            __half2* hxp = (__half2*)(hx_out + gi);
            hxp[0] = __floats2half2_rn(h4.x, h4.y);
            hxp[1] = __floats2half2_rn(h4.z, h4.w);
        }
        __syncthreads();                                 // hx visible block-wide
        if (t < TT - 1 && tid == 0) {                    // early release
            unsigned nv = fbase + (unsigned)(t + 1);
            asm volatile("st.release.gpu.global.u32 [%0], %1;"
                         :: "l"(&g_arrive[mt][ng]), "r"(nv) : "memory");
        }
        // fp32 outputs after release (not on peers' critical path)
        *(float4*)(out + ((size_t)t * BBATCH + m0 + um) * HHID + h0 + uj) = h4;
        if (t == TT - 1) {
            *(float4*)(out + STACKED_SZ + gi) = h4;
            *(float4*)(out + STACKED_SZ + STATE_SZ + gi) = c4v;
        }
    }
    CP_WAIT(0);   // drain the final dummy prefetch before exit
}

// ---------------------------------------------------------------------------
extern "C" void kernel_launch(void* const* d_in, const int* in_sizes, int n_in,
                              void* d_out, int out_size)
{
    (void)in_sizes; (void)n_in; (void)out_size;
    const float* inputs = (const float*)d_in[0];
    const float* ew1 = (const float*)d_in[1];
    const float* eb1 = (const float*)d_in[2];
    const float* ew2 = (const float*)d_in[3];
    const float* eb2 = (const float*)d_in[4];
    const float* ew3 = (const float*)d_in[5];
    const float* eb3 = (const float*)d_in[6];
    const float* gw  = (const float*)d_in[7];
    const float* gb  = (const float*)d_in[8];
    const float* sw1 = (const float*)d_in[9];
    const float* sb1 = (const float*)d_in[10];
    const float* sw2 = (const float*)d_in[11];
    const float* sb2 = (const float*)d_in[12];
    float* out = (float*)d_out;

    void *ph1, *ph2, *pwp, *pbp;
    cudaGetSymbolAddress(&ph1, d_h1);
    cudaGetSymbolAddress(&ph2, d_h2h);
    cudaGetSymbolAddress(&pwp, d_wp);
    cudaGetSymbolAddress(&pbp, d_bp);

    cudaFuncSetAttribute((const void*)lstm_persistent,
                         cudaFuncAttributeMaxDynamicSharedMemorySize,
                         PS_SMEM_BYTES);

    mask_kernel<<<1, 32>>>(sw1, sb1, sw2, sb2);
    wprime_kernel<<<32, 256>>>(ew3, gw, (float*)pwp);
    bprime_kernel<<<64, 32>>>(eb3, gw, gb, (float*)pbp);

    dim3 tb(128);
    // h1 = relu(x @ w1 + b1)              [65536,512]x[512,128], fp32 out
    gemm_tf32_kernel<1, 0><<<dim3(2, MROWS / 64), tb>>>(
        inputs, ew1, eb1, ph1, MROWS, 128, 512, 128);
    // h2 = fp16(relu(h1 @ w2 + b2))       [65536,128]x[128,64], half out
    gemm_tf32_kernel<1, 1><<<dim3(1, MROWS / 64), tb>>>(
        (const float*)ph1, ew2, eb2, ph2, MROWS, 64, 128, 64);

    // persistent fused recurrence (decentralized polling pipeline)
    lstm_persistent<<<128, 256, PS_SMEM_BYTES>>>(
        gw, (const float*)pwp, (const float*)pbp, out);
}

// round 16
// speedup vs baseline: 2.4993x; 2.4993x over previous
#include <cuda_runtime.h>
#include <cuda_fp16.h>
#include <math.h>
#include <stdint.h>

#define TT      256
#define BBATCH  256
#define HHID    512
#define MROWS   65536
#define NGATE   2048
#define STATE_SZ (BBATCH*HHID)
#define STACKED_SZ ((size_t)TT*BBATCH*HHID)

__device__ float  d_h1[(size_t)MROWS * 128];
__device__ __half d_h2h[(size_t)MROWS * 64];
__device__ float  d_wp[(size_t)64 * NGATE];
__device__ float  d_bp[NGATE];
__device__ __half d_hxh[2][STATE_SZ];
__device__ float  d_mask[4];
__device__ unsigned g_arrive[4][32];   // monotone per-(mt,ng) step counters

__device__ __forceinline__ float ftf32(float x) {
    float r; asm("cvt.rna.tf32.f32 %0, %1;" : "=f"(r) : "f"(x)); return r;
}
__device__ __forceinline__ void mma8(float c[4],
                                     uint32_t a0, uint32_t a1, uint32_t a2, uint32_t a3,
                                     uint32_t b0, uint32_t b1) {
    asm volatile(
        "mma.sync.aligned.m16n8k8.row.col.f32.tf32.tf32.f32 "
        "{%0,%1,%2,%3},{%4,%5,%6,%7},{%8,%9},{%0,%1,%2,%3};\n"
        : "+f"(c[0]), "+f"(c[1]), "+f"(c[2]), "+f"(c[3])
        : "r"(a0), "r"(a1), "r"(a2), "r"(a3), "r"(b0), "r"(b1));
}
__device__ __forceinline__ void mma16(float c[4],
                                      uint32_t a0, uint32_t a1, uint32_t a2, uint32_t a3,
                                      uint32_t b0, uint32_t b1) {
    asm volatile(
        "mma.sync.aligned.m16n8k16.row.col.f32.f16.f16.f32 "
        "{%0,%1,%2,%3},{%4,%5,%6,%7},{%8,%9},{%0,%1,%2,%3};\n"
        : "+f"(c[0]), "+f"(c[1]), "+f"(c[2]), "+f"(c[3])
        : "r"(a0), "r"(a1), "r"(a2), "r"(a3), "r"(b0), "r"(b1));
}
__device__ __forceinline__ void ldsm4(uint32_t& r0, uint32_t& r1, uint32_t& r2,
                                      uint32_t& r3, uint32_t a) {
    asm volatile("ldmatrix.sync.aligned.m8n8.x4.shared.b16 {%0,%1,%2,%3}, [%4];"
                 : "=r"(r0), "=r"(r1), "=r"(r2), "=r"(r3) : "r"(a));
}
__device__ __forceinline__ void cpa16(uint32_t dst, const void* src) {
    asm volatile("cp.async.cg.shared.global [%0], [%1], 16;\n" :: "r"(dst), "l"(src));
}
#define CP_COMMIT() asm volatile("cp.async.commit_group;\n" ::: "memory")
#define CP_WAIT(n)  asm volatile("cp.async.wait_group %0;\n" :: "n"(n) : "memory")

__device__ __forceinline__ float fsig(float x) {
    return __fdividef(1.f, 1.f + __expf(-x));
}
__device__ __forceinline__ float ftanh(float x) {
    return __fdividef(2.f, 1.f + __expf(-2.f * x)) - 1.f;
}

// ---------------------------------------------------------------------------
// Encoder tf32 GEMM (proven, unchanged)
// ---------------------------------------------------------------------------
template<int RELU, int OUTH>
__global__ void __launch_bounds__(128) gemm_tf32_kernel(
    const float* __restrict__ A, const float* __restrict__ B,
    const float* __restrict__ bias, void* __restrict__ Cv,
    int M, int N, int K, int ldb)
{
    __shared__ float As[2][2304];
    __shared__ float Bs[2][2304];

    const int tid = threadIdx.x;
    const int lane = tid & 31, warp = tid >> 5;
    const int m0 = blockIdx.y * 64, n0 = blockIdx.x * 64;
    const int wm = (warp >> 1) * 32, wn = (warp & 1) * 32;
    const int g = lane >> 2, tg = lane & 3;

    float acc[2][4][4];
#pragma unroll
    for (int i = 0; i < 2; i++)
#pragma unroll
        for (int j = 0; j < 4; j++)
#pragma unroll
            for (int e = 0; e < 4; e++) acc[i][j][e] = 0.f;

    const int NC = K >> 5;
    float4 ra[4], rb[4];

    auto loadg = [&](int kc) {
#pragma unroll
        for (int p = 0; p < 4; p++) {
            int idx = p * 512 + tid * 4;
            int am = idx >> 5, ak = idx & 31;
            ra[p] = *(const float4*)(A + (size_t)(m0 + am) * K + kc + ak);
            int bk = idx >> 6, bn = idx & 63;
            rb[p] = *(const float4*)(B + (size_t)(kc + bk) * ldb + n0 + bn);
        }
    };
    auto store = [&](int buf) {
#pragma unroll
        for (int p = 0; p < 4; p++) {
            int idx = p * 512 + tid * 4;
            int am = idx >> 5, ak = idx & 31;
            float4 v = ra[p];
            v.x = ftf32(v.x); v.y = ftf32(v.y); v.z = ftf32(v.z); v.w = ftf32(v.w);
            *(float4*)&As[buf][am * 36 + ak] = v;
            int bk = idx >> 6, bn = idx & 63;
            float4 w = rb[p];
            w.x = ftf32(w.x); w.y = ftf32(w.y); w.z = ftf32(w.z); w.w = ftf32(w.w);
            *(float4*)&Bs[buf][bk * 72 + bn] = w;
        }
    };
    auto compute = [&](int buf) {
#pragma unroll
        for (int kk = 0; kk < 32; kk += 8) {
            uint32_t a[2][4];
#pragma unroll
            for (int mf = 0; mf < 2; mf++) {
                int rbase = wm + mf * 16 + g;
                a[mf][0] = __float_as_uint(As[buf][rbase * 36 + kk + tg]);
                a[mf][1] = __float_as_uint(As[buf][(rbase + 8) * 36 + kk + tg]);
                a[mf][2] = __float_as_uint(As[buf][rbase * 36 + kk + tg + 4]);
                a[mf][3] = __float_as_uint(As[buf][(rbase + 8) * 36 + kk + tg + 4]);
            }
#pragma unroll
            for (int nf = 0; nf < 4; nf++) {
                uint32_t b0 = __float_as_uint(Bs[buf][(kk + tg) * 72 + wn + nf * 8 + g]);
                uint32_t b1 = __float_as_uint(Bs[buf][(kk + tg + 4) * 72 + wn + nf * 8 + g]);
                mma8(acc[0][nf], a[0][0], a[0][1], a[0][2], a[0][3], b0, b1);
                mma8(acc[1][nf], a[1][0], a[1][1], a[1][2], a[1][3], b0, b1);
            }
        }
    };

    loadg(0); store(0); __syncthreads();
    for (int c = 0; c < NC; c++) {
        int cur = c & 1;
        if (c + 1 < NC) loadg((c + 1) * 32);
        compute(cur);
        if (c + 1 < NC) store(cur ^ 1);
        __syncthreads();
    }

#pragma unroll
    for (int mf = 0; mf < 2; mf++) {
        int r = m0 + wm + mf * 16 + g;
#pragma unroll
        for (int nf = 0; nf < 4; nf++) {
            int col = n0 + wn + nf * 8 + 2 * tg;
            float b0 = bias[col], b1 = bias[col + 1];
            float v0 = acc[mf][nf][0] + b0;
            float v1 = acc[mf][nf][1] + b1;
            float v2 = acc[mf][nf][2] + b0;
            float v3 = acc[mf][nf][3] + b1;
            if (RELU) {
                v0 = fmaxf(v0, 0.f); v1 = fmaxf(v1, 0.f);
                v2 = fmaxf(v2, 0.f); v3 = fmaxf(v3, 0.f);
            }
            if (OUTH) {
                __half* C = (__half*)Cv;
                *(__half2*)(C + (size_t)r * N + col)       = __floats2half2_rn(v0, v1);
                *(__half2*)(C + (size_t)(r + 8) * N + col) = __floats2half2_rn(v2, v3);
            } else {
                float* C = (float*)Cv;
                float2 p0; p0.x = v0; p0.y = v1;
                float2 p1; p1.x = v2; p1.y = v3;
                *(float2*)(C + (size_t)r * N + col) = p0;
                *(float2*)(C + (size_t)(r + 8) * N + col) = p1;
            }
        }
    }
}

// ---------------------------------------------------------------------------
// W' = enc_w3 @ gate_w[0:512]  (fp32), with bprime and the sampler mask
// folded in (bprime reuses the staged GW tiles; identical k order -> bit-
// identical results to the old separate kernels).
// ---------------------------------------------------------------------------
__global__ void __launch_bounds__(256) wprime_kernel(
    const float* __restrict__ W3, const float* __restrict__ GW,
    float* __restrict__ WP,
    const float* __restrict__ eb3, const float* __restrict__ gb,
    float* __restrict__ BP,
    const float* __restrict__ sw1, const float* __restrict__ sb1,
    const float* __restrict__ sw2, const float* __restrict__ sb2)
{
    __shared__ float Asw[64][33];
    __shared__ float Bsw[32][65];
    __shared__ float eb3s[32];
    int tid = threadIdx.x;
    int n0 = blockIdx.x * 64;
    int col = tid & 63;
    int rg = (tid >> 6) * 16;
    float acc[16];
#pragma unroll
    for (int i = 0; i < 16; i++) acc[i] = 0.f;
    float accb = 0.f;

    for (int kc = 0; kc < 512; kc += 32) {
#pragma unroll
        for (int p = 0; p < 8; p++) {
            int idx = p * 256 + tid;
            int r = idx >> 5, k = idx & 31;
            Asw[r][k] = W3[(size_t)r * 512 + kc + k];
            int bk = idx >> 6, bc = idx & 63;
            Bsw[bk][bc] = GW[(size_t)(kc + bk) * NGATE + n0 + bc];
        }
        if (tid < 32) eb3s[tid] = eb3[kc + tid];
        __syncthreads();
#pragma unroll 8
        for (int k = 0; k < 32; k++) {
            float bv = Bsw[k][col];
#pragma unroll
            for (int i = 0; i < 16; i++) acc[i] += Asw[rg + i][k] * bv;
        }
        if (tid < 64) {
#pragma unroll 8
            for (int k = 0; k < 32; k++) accb += eb3s[k] * Bsw[k][tid];
        }
        __syncthreads();
    }
#pragma unroll
    for (int i = 0; i < 16; i++)
        WP[(size_t)(rg + i) * NGATE + n0 + col] = acc[i];
    if (tid < 64) BP[n0 + tid] = accb + gb[n0 + tid];

    // sampler mask (input-invariant), one thread
    if (blockIdx.x == 0 && tid == 255) {
        float h[8];
        for (int j = 0; j < 8; j++) {
            float s = sb1[j];
            for (int i = 0; i < 4; i++) s += sw1[i * 8 + j];
            h[j] = tanhf(s);
        }
        float o[4], mx = -1e30f;
        for (int k = 0; k < 4; k++) {
            float s = sb2[k];
            for (int j = 0; j < 8; j++) s += h[j] * sw2[j * 4 + k];
            o[k] = s; mx = fmaxf(mx, s);
        }
        float e[4], se = 0.f;
        for (int k = 0; k < 4; k++) { e[k] = expf(o[k] - mx); se += e[k]; }
        for (int k = 0; k < 4; k++) d_mask[k] = e[k] / se;
    }
}

// ---------------------------------------------------------------------------
// Persistent recurrence: R14 EXACT (proven 1266 us), plus last-step dummy
// h2-prefetch skipped (CP_WAIT counts corrected).
// ---------------------------------------------------------------------------
#define PS_SMEM_BYTES 166144
#define A_OFF   74752
#define H2_OFF  140288
#define GSM_OFF 148480
#define BSM_OFF 165888

__global__ void __launch_bounds__(256) lstm_persistent(
    const float* __restrict__ gate_w, const float* __restrict__ wp,
    const float* __restrict__ bp, float* __restrict__ out)
{
    extern __shared__ __align__(16) char smem[];
    __half* Bs  = (__half*)smem;
    float*  gsm = (float*)(smem + GSM_OFF);
    float*  bsm = (float*)(smem + BSM_OFF);
    const uint32_t sbase = (uint32_t)__cvta_generic_to_shared(smem);

    const int tid  = threadIdx.x;
    const int lane = tid & 31, warp = tid >> 5;
    const int g = lane >> 2, tg = lane & 3;
    const int gate = warp & 3;
    const int wn = gate * 16;
    const int wm = (warp >> 2) * 32;

    const int ng = blockIdx.x & 31;     // 16 h cols
    const int mt = blockIdx.x >> 5;     // m-tile
    const int m0 = mt * 64;
    const int h0 = ng * 16;

    const float* Wh = gate_w + (size_t)512 * NGATE;

    unsigned fbase = *((volatile unsigned*)&g_arrive[mt][ng]);

    // ---- preload weights into Bs[n][k] (half), k<512 Wh, k>=512 W' ----
    for (int it = tid; it < 64 * 576; it += 256) {
        int n = it & 63;
        int k = it >> 6;
        int gt = n >> 4, j = n & 15;
        float v;
        if (k < 512) v = Wh[(size_t)k * NGATE + gt * 512 + h0 + j];
        else         v = wp[(size_t)(k - 512) * NGATE + gt * 512 + h0 + j];
        Bs[n * 584 + k] = __float2half_rn(v);
    }
    if (tid < 64) {
        int gt = tid >> 4, j = tid & 15;
        bsm[tid] = bp[gt * 512 + h0 + j];
    }
    __syncthreads();

    const float mk = d_mask[gate];
    float cx[4] = {0.f, 0.f, 0.f, 0.f};
    const int um = tid >> 2, uj = (tid & 3) * 4;

    auto issueA_nc = [&](int buf, const __half* src) {
#pragma unroll
        for (int p = 0; p < 4; p++) {
            int idx = p * 256 + tid;
            int row = idx >> 4, gr = idx & 15;
            uint32_t dst = sbase + (uint32_t)(A_OFF + buf * 16384 + row * 256
                                              + ((gr ^ (row & 7)) << 4));
            cpa16(dst, src + (size_t)row * HHID + gr * 8);
        }
    };
    auto issueH2 = [&](const __half* src) {
#pragma unroll
        for (int p = 0; p < 2; p++) {
            int idx = p * 256 + tid;
            int row = idx >> 3, gr = idx & 7;
            uint32_t dst = sbase + (uint32_t)(H2_OFF + row * 128
                                              + ((gr ^ (row & 7)) << 4));
            cpa16(dst, src + (size_t)row * 64 + gr * 8);
        }
        CP_COMMIT();
    };

    float acc[2][2][4];
    const int mi = lane >> 3;
    const int rA0 = wm + (mi & 1) * 8 + (lane & 7);
    const uint32_t bbase = sbase
        + (uint32_t)(((wn + (mi >> 1) * 8 + (lane & 7)) * 584 + (mi & 1) * 8) * 2);
    auto computeL = [&](uint32_t aoff, int RS, int koff, int ks, int NKK) {
        for (int kk16 = ks; kk16 < ks + NKK; kk16++) {
            const int kg = kk16 * 2 + (mi >> 1);
            uint32_t a0, a1, a2, a3, c0, c1, c2, c3;
            {
                int row = rA0;
                uint32_t ad = sbase + aoff
                    + (uint32_t)((row * RS + ((kg ^ (row & 7)) << 3)) << 1);
                ldsm4(a0, a1, a2, a3, ad);
            }
            {
                int row = rA0 + 16;
                uint32_t ad = sbase + aoff
                    + (uint32_t)((row * RS + ((kg ^ (row & 7)) << 3)) << 1);
                ldsm4(c0, c1, c2, c3, ad);
            }
            uint32_t b0, b1, b2, b3;
            ldsm4(b0, b1, b2, b3, bbase + (uint32_t)((koff + kk16 * 16) * 2));
            mma16(acc[0][0], a0, a1, a2, a3, b0, b1);
            mma16(acc[1][0], c0, c1, c2, c3, b0, b1);
            mma16(acc[0][1], a0, a1, a2, a3, b2, b3);
            mma16(acc[1][1], c0, c1, c2, c3, b2, b3);
        }
    };

    // prologue: h2[0] -> h2 buffer
    issueH2(d_h2h + (size_t)m0 * 64);

    for (int t = 0; t < TT; t++) {
        const __half* hx_in  = d_hxh[t & 1];
        __half*       hx_out = d_hxh[(t + 1) & 1];

#pragma unroll
        for (int i = 0; i < 2; i++)
#pragma unroll
            for (int j = 0; j < 2; j++)
#pragma unroll
                for (int e = 0; e < 4; e++) acc[i][j][e] = 0.f;

        CP_WAIT(0);
        __syncthreads();

        if (t == 0) {
            computeL(H2_OFF, 64, 512, 0, 4);             // full chunk 0 (hx=0)
            __syncthreads();                             // all H2 reads done
            issueH2(d_h2h + (size_t)(BBATCH + m0) * 64); // h2[1]
        } else {
            computeL(H2_OFF, 64, 512, 0, 2);             // chunk0 part 1
            // acquire step-t hx from all 32 producers (single coalesced warp)
            if (tid < 32) {
                unsigned tgt = fbase + (unsigned)t;
                const unsigned* fp = &g_arrive[mt][tid];
                unsigned v;
                do {
                    asm volatile("ld.acquire.gpu.global.u32 %0, [%1];"
                                 : "=r"(v) : "l"(fp));
                } while ((int)(v - tgt) < 0);
            }
            __syncthreads();
            const __half* hxm = hx_in + (size_t)m0 * HHID;
            issueA_nc(0, hxm);     issueA_nc(1, hxm + 128); CP_COMMIT();   // G1
            issueA_nc(2, hxm + 256); issueA_nc(3, hxm + 384); CP_COMMIT(); // G2
            computeL(H2_OFF, 64, 512, 2, 2);             // chunk0 part 2 (hides G1)

            CP_WAIT(1); __syncthreads();                 // G1 ready; H2 reads retired
            if (t + 1 < TT)                              // G3: h2[t+1] prefetch
                issueH2(d_h2h + ((size_t)(t + 1) * BBATCH + m0) * 64);
            computeL(A_OFF,         128, 0,   0, 8);     // c1
            computeL(A_OFF + 16384, 128, 128, 0, 8);     // c2
            if (t + 1 < TT) { CP_WAIT(1); } else { CP_WAIT(0); }  // G2 ready
            __syncthreads();
            computeL(A_OFF + 32768, 128, 256, 0, 8);     // c3
            computeL(A_OFF + 49152, 128, 384, 0, 8);     // c4
        }

        // ---- epilogue: bias + activation*mask -> gsm (own warp tile) ----
#pragma unroll
        for (int mf = 0; mf < 2; mf++) {
            int r0 = wm + mf * 16 + g;
#pragma unroll
            for (int nf = 0; nf < 2; nf++) {
                int j0 = nf * 8 + 2 * tg;
                float b0 = bsm[gate * 16 + j0], b1 = bsm[gate * 16 + j0 + 1];
                float p0 = acc[mf][nf][0] + b0;
                float p1 = acc[mf][nf][1] + b1;
                float p2 = acc[mf][nf][2] + b0;
                float p3 = acc[mf][nf][3] + b1;
                float a0, a1, a2, a3;
                if (gate == 2) {
                    a0 = ftanh(p0); a1 = ftanh(p1); a2 = ftanh(p2); a3 = ftanh(p3);
                } else {
                    a0 = fsig(p0); a1 = fsig(p1); a2 = fsig(p2); a3 = fsig(p3);
                }
                float* gp = gsm + gate * 1088;
                gp[r0 * 17 + j0]           = a0 * mk;
                gp[r0 * 17 + j0 + 1]       = a1 * mk;
                gp[(r0 + 8) * 17 + j0]     = a2 * mk;
                gp[(r0 + 8) * 17 + j0 + 1] = a3 * mk;
            }
        }
        __syncthreads();

        // ---- cell update (cx register-resident); hx fp16 store first ----
        float4 h4, c4v;
        float* hp = &h4.x; float* cp = &c4v.x;
#pragma unroll
        for (int q = 0; q < 4; q++) {
            int jj = uj + q;
            float fv = gsm[0 * 1088 + um * 17 + jj];
            float iv = gsm[1 * 1088 + um * 17 + jj];
            float gv = gsm[2 * 1088 + um * 17 + jj];
            float ov = gsm[3 * 1088 + um * 17 + jj];
            cx[q] = fv * cx[q] + iv * gv;
            cp[q] = cx[q];
            hp[q] = ov * ftanh(cx[q]);
        }
        int gi = (m0 + um) * HHID + h0 + uj;
        {
            __half2* hxp = (__half2*)(hx_out + gi);
            hxp[0] = __floats2half2_rn(h4.x, h4.y);
            hxp[1] = __floats2half2_rn(h4.z, h4.w);
        }
        __syncthreads();                                 // hx visible block-wide
        if (t < TT - 1 && tid == 0) {                    // early release
            unsigned nv = fbase + (unsigned)(t + 1);
            asm volatile("st.release.gpu.global.u32 [%0], %1;"
                         :: "l"(&g_arrive[mt][ng]), "r"(nv) : "memory");
        }
        // fp32 outputs after release (not on peers' critical path)
        *(float4*)(out + ((size_t)t * BBATCH + m0 + um) * HHID + h0 + uj) = h4;
        if (t == TT - 1) {
            *(float4*)(out + STACKED_SZ + gi) = h4;
            *(float4*)(out + STACKED_SZ + STATE_SZ + gi) = c4v;
        }
    }
    CP_WAIT(0);
}

// ---------------------------------------------------------------------------
extern "C" void kernel_launch(void* const* d_in, const int* in_sizes, int n_in,
                              void* d_out, int out_size)
{
    (void)in_sizes; (void)n_in; (void)out_size;
    const float* inputs = (const float*)d_in[0];
    const float* ew1 = (const float*)d_in[1];
    const float* eb1 = (const float*)d_in[2];
    const float* ew2 = (const float*)d_in[3];
    const float* eb2 = (const float*)d_in[4];
    const float* ew3 = (const float*)d_in[5];
    const float* eb3 = (const float*)d_in[6];
    const float* gw  = (const float*)d_in[7];
    const float* gb  = (const float*)d_in[8];
    const float* sw1 = (const float*)d_in[9];
    const float* sb1 = (const float*)d_in[10];
    const float* sw2 = (const float*)d_in[11];
    const float* sb2 = (const float*)d_in[12];
    float* out = (float*)d_out;

    void *ph1, *ph2, *pwp, *pbp;
    cudaGetSymbolAddress(&ph1, d_h1);
    cudaGetSymbolAddress(&ph2, d_h2h);
    cudaGetSymbolAddress(&pwp, d_wp);
    cudaGetSymbolAddress(&pbp, d_bp);

    cudaFuncSetAttribute((const void*)lstm_persistent,
                         cudaFuncAttributeMaxDynamicSharedMemorySize,
                         PS_SMEM_BYTES);

    // W' + b' + sampler mask in one launch
    wprime_kernel<<<32, 256>>>(ew3, gw, (float*)pwp,
                               eb3, gb, (float*)pbp,
                               sw1, sb1, sw2, sb2);

    dim3 tb(128);
    // h1 = relu(x @ w1 + b1)              [65536,512]x[512,128], fp32 out
    gemm_tf32_kernel<1, 0><<<dim3(2, MROWS / 64), tb>>>(
        inputs, ew1, eb1, ph1, MROWS, 128, 512, 128);
    // h2 = fp16(relu(h1 @ w2 + b2))       [65536,128]x[128,64], half out
    gemm_tf32_kernel<1, 1><<<dim3(1, MROWS / 64), tb>>>(
        (const float*)ph1, ew2, eb2, ph2, MROWS, 64, 128, 64);

    // persistent fused recurrence (R14 pipeline)
    lstm_persistent<<<128, 256, PS_SMEM_BYTES>>>(
        gw, (const float*)pwp, (const float*)pbp, out);
}